// round 8
// baseline (speedup 1.0000x reference)
#include <cuda_runtime.h>
#include <cuda_bf16.h>
#include <cuda_fp16.h>
#include <stdint.h>

// Problem constants
#define BB  16
#define DD  256
#define HH  32
#define WW  32
#define NN  16384
#define KK  8192
#define CHW (DD*HH*WW)
#define HW  (HH*WW)

#define NCHUNK  128
#define GSZ     16
#define NGRP    (KK/GSZ)       // 512
#define MARGIN  1.0e-3f        // fp8 approx error budget (~11 sigma)
#define PAIR_CAP (NN*64)
#define ESCALE  4096.0f        // e scaled by 2^12 before e4m3 (exact)
#define DSCALE  (-4.8828125e-4f)   // -2/4096

#define SMEM_MMA 65536         // z tile 2x16KB + e double-buffer 2x16KB

// ---------------- device scratch (static globals; no allocation) -----------
__device__ __align__(16) float    g_zt[NN*DD];   // transposed z fp32 [n][d]
__device__ __align__(16) uint8_t  g_z8[NN*DD];   // e4m3(z) [n][d]
__device__ __align__(16) uint8_t  g_e8[KK*DD];   // e4m3(e*4096) [k][d]
__device__ float          g_z2[NN];
__device__ float          g_e2[KK];
__device__ __align__(16) __half g_gmin[(size_t)NN*NGRP]; // [row][group] rd-fp16 min of (e2-2dot)
__device__ unsigned long long g_best[NN];
__device__ unsigned int   g_pairs[PAIR_CAP];
__device__ int            g_count;
__device__ float          g_partial[512];

// ---------------- helpers ---------------------------------------------------
__device__ __forceinline__ uint32_t smem_u32(const void* p) {
    uint32_t a;
    asm("{ .reg .u64 t; cvta.to.shared.u64 t, %1; cvt.u32.u64 %0, t; }" : "=r"(a) : "l"(p));
    return a;
}
__device__ __forceinline__ void ldsm4(uint32_t* r, uint32_t addr) {
    asm volatile("ldmatrix.sync.aligned.m8n8.x4.shared.b16 {%0,%1,%2,%3}, [%4];"
                 : "=r"(r[0]), "=r"(r[1]), "=r"(r[2]), "=r"(r[3]) : "r"(addr));
}
__device__ __forceinline__ void ldsm2(uint32_t* r, uint32_t addr) {
    asm volatile("ldmatrix.sync.aligned.m8n8.x2.shared.b16 {%0,%1}, [%2];"
                 : "=r"(r[0]), "=r"(r[1]) : "r"(addr));
}
__device__ __forceinline__ void mma_fp8(float* c, const uint32_t* a, const uint32_t* b) {
    asm volatile("mma.sync.aligned.m16n8k32.row.col.f32.e4m3.e4m3.f32 "
                 "{%0,%1,%2,%3}, {%4,%5,%6,%7}, {%8,%9}, {%0,%1,%2,%3};"
                 : "+f"(c[0]), "+f"(c[1]), "+f"(c[2]), "+f"(c[3])
                 : "r"(a[0]), "r"(a[1]), "r"(a[2]), "r"(a[3]), "r"(b[0]), "r"(b[1]));
}
__device__ __forceinline__ void cp16(uint32_t dst, const void* src) {
    asm volatile("cp.async.cg.shared.global [%0], [%1], 16;" :: "r"(dst), "l"(src));
}
__device__ __forceinline__ uint8_t f2e4m3(float x) {
    uint16_t r;
    asm("{ .reg .b16 t; cvt.rn.satfinite.e4m3x2.f32 t, %1, %2; mov.b16 %0, t; }"
        : "=h"(r) : "f"(0.f), "f"(x));
    return (uint8_t)(r & 0xFF);
}

// ---------------- prep: transpose z + fp8 cast + z2 -------------------------
__global__ void __launch_bounds__(256) k_transpose(const float* __restrict__ z) {
    __shared__ float ts[256][33];
    int t = threadIdx.x, lane = t & 31, w = t >> 5;
    int n0 = blockIdx.x * 32;
    int b = n0 >> 10, s0 = n0 & 1023;
    const float* zp = z + (size_t)b * CHW + s0;
#pragma unroll 8
    for (int j = 0; j < 32; j++) {
        int d = j * 8 + w;
        ts[d][lane] = zp[(size_t)d * HW + lane];
    }
    __syncthreads();
#pragma unroll 8
    for (int j = 0; j < 32; j++) {
        float v = ts[t][j];
        size_t o = (size_t)(n0 + j) * DD + t;
        g_zt[o] = v;
        g_z8[o] = f2e4m3(v);
    }
#pragma unroll
    for (int q = 0; q < 4; q++) {
        int nl = w * 4 + q;
        float s = 0.f;
#pragma unroll
        for (int jj = 0; jj < 8; jj++) { float v = ts[lane + 32 * jj][nl]; s = fmaf(v, v, s); }
#pragma unroll
        for (int m = 16; m; m >>= 1) s += __shfl_xor_sync(0xffffffffu, s, m);
        if (lane == 0) g_z2[n0 + nl] = s;
    }
}

// prep: fp8 cast of scaled embeddings + e2 ; also zero pair counter
__global__ void __launch_bounds__(256) k_prep_e(const float* __restrict__ emb) {
    if (blockIdx.x == 0 && threadIdx.x == 0) g_count = 0;
    int k = blockIdx.x * 8 + (threadIdx.x >> 5);
    int lane = threadIdx.x & 31;
    const float* p = emb + (size_t)k * DD;
    float sum = 0.f;
#pragma unroll
    for (int j = 0; j < DD / 32; j++) {
        float v = p[lane + 32 * j];
        sum = fmaf(v, v, sum);
        g_e8[(size_t)k * DD + lane + 32 * j] = f2e4m3(v * ESCALE);
    }
#pragma unroll
    for (int m = 16; m; m >>= 1) sum += __shfl_xor_sync(0xffffffffu, sum, m);
    if (lane == 0) g_e2[k] = sum;
}

// ---------------- phase 1: fp8 HMMA GEMM + per-group min --------------------
// smem: [0,32KB) z tile (2 subtiles of 128x128B), [32KB,64KB) e double buffer.
__device__ __forceinline__ void stage_e(uint32_t sb, int s, int c0, int t) {
    int cc = s >> 1, dc = s & 1;
    const uint8_t* esrc = g_e8 + (size_t)(c0 + cc) * NCHUNK * DD + dc * 128;
    uint32_t eb = sb + 32768u + (uint32_t)(s & 1) * 16384u;
#pragma unroll
    for (int j = 0; j < 4; j++) {
        int f = t + j * 256;               // 0..1023 16B chunks
        int r = f >> 3, ch = f & 7;
        cp16(eb + (uint32_t)(r * 128 + ((ch ^ (r & 7)) << 4)),
             esrc + (size_t)r * DD + ch * 16);
    }
    asm volatile("cp.async.commit_group;" ::: "memory");
}

__global__ void __launch_bounds__(256, 2) k_mma() {
    extern __shared__ __align__(1024) char smem[];
    uint32_t sb = smem_u32(smem);

    int t = threadIdx.x, lane = t & 31, wid = t >> 5;
    int wm = wid >> 2, wn = wid & 3;          // 2x4 warp grid, warp tile 64x32
    int n0 = blockIdx.x * 128;
    int c0 = blockIdx.y * 32;

    // z tile once: 128 rows x 256 fp8 = 32KB, subtile per 128-dim half
    {
        const uint8_t* zsrc = g_z8 + (size_t)n0 * DD;
#pragma unroll
        for (int j = 0; j < 8; j++) {
            int f = t + j * 256;              // 0..2047 16B chunks
            int r = f >> 4, c16 = f & 15;
            int dcs = c16 >> 3, ch = c16 & 7;
            cp16(sb + (uint32_t)(dcs * 16384 + r * 128 + ((ch ^ (r & 7)) << 4)),
                 zsrc + (size_t)r * DD + c16 * 16);
        }
    }
    stage_e(sb, 0, c0, t);                    // G0 = z + e-stage0

    int sub  = lane >> 3;
    int arow = wm * 64 + ((sub & 1) << 3) + (lane & 7);  // + mi*16
    int acoff = sub >> 1;
    int brow = wn * 32 + (lane & 7);                     // + ni*8
    int bsub = (lane >> 3) & 1;

    for (int cc = 0; cc < 32; cc++) {
        int c = c0 + cc;
        float acc[4][4][4];
#pragma unroll
        for (int mi = 0; mi < 4; mi++)
#pragma unroll
            for (int ni = 0; ni < 4; ni++)
#pragma unroll
                for (int q = 0; q < 4; q++) acc[mi][ni][q] = 0.f;

#pragma unroll
        for (int dc = 0; dc < 2; dc++) {
            int s = cc * 2 + dc;
            if (s + 1 < 64) {
                stage_e(sb, s + 1, c0, t);
                asm volatile("cp.async.wait_group 1;" ::: "memory");
            } else {
                asm volatile("cp.async.wait_group 0;" ::: "memory");
            }
            __syncthreads();
            uint32_t zb = sb + (uint32_t)dc * 16384u;              // z subtile = dc
            uint32_t eb = sb + 32768u + (uint32_t)(s & 1) * 16384u;
#pragma unroll
            for (int ks = 0; ks < 4; ks++) {
                uint32_t b[4][2];
#pragma unroll
                for (int ni = 0; ni < 4; ni++) {
                    int row = brow + ni * 8;
                    int ci  = ks * 2 + bsub;
                    ldsm2(b[ni], eb + (uint32_t)(row * 128 + ((ci ^ (row & 7)) << 4)));
                }
#pragma unroll
                for (int mi = 0; mi < 4; mi++) {
                    uint32_t a4[4];
                    int row = arow + mi * 16;
                    int ci  = ks * 2 + acoff;
                    ldsm4(a4, zb + (uint32_t)(row * 128 + ((ci ^ (row & 7)) << 4)));
#pragma unroll
                    for (int ni = 0; ni < 4; ni++)
                        mma_fp8(acc[mi][ni], a4, b[ni]);
                }
            }
            __syncthreads();       // e buffer (s&1) reusable at s+2
        }
        // epilogue: per-row per-16-col-group min of (e2 - 2*dot), fp16 rd store
        float e2r[8];
#pragma unroll
        for (int ni = 0; ni < 4; ni++)
#pragma unroll
            for (int h = 0; h < 2; h++)
                e2r[ni * 2 + h] = __ldg(&g_e2[c * NCHUNK + wn * 32 + ni * 8 + (lane & 3) * 2 + h]);
#pragma unroll
        for (int mi = 0; mi < 4; mi++)
#pragma unroll
            for (int rh = 0; rh < 2; rh++) {
                float mp0 = 3.4e38f, mp1 = 3.4e38f;
#pragma unroll
                for (int ni = 0; ni < 4; ni++)
#pragma unroll
                    for (int h = 0; h < 2; h++) {
                        float dv = fmaf(DSCALE, acc[mi][ni][rh * 2 + h], e2r[ni * 2 + h]);
                        if (ni < 2) { if (dv < mp0) mp0 = dv; }
                        else        { if (dv < mp1) mp1 = dv; }
                    }
                mp0 = fminf(mp0, __shfl_xor_sync(0xffffffffu, mp0, 1));
                mp0 = fminf(mp0, __shfl_xor_sync(0xffffffffu, mp0, 2));
                mp1 = fminf(mp1, __shfl_xor_sync(0xffffffffu, mp1, 1));
                mp1 = fminf(mp1, __shfl_xor_sync(0xffffffffu, mp1, 2));
                if ((lane & 3) == 0) {
                    int row = n0 + wm * 64 + mi * 16 + rh * 8 + (lane >> 2);
                    size_t base = (size_t)row * NGRP + c * 8 + wn * 2;
                    __half2 hv;
                    hv.x = __float2half_rd(mp0);
                    hv.y = __float2half_rd(mp1);
                    *(__half2*)(g_gmin + base) = hv;
                }
            }
    }
}

// ---------------- phase 2a: scan gmin (fp16), emit candidate pairs ----------
__global__ void __launch_bounds__(256) k_gap() {
    int wid = threadIdx.x >> 5, lane = threadIdx.x & 31;
    int row = blockIdx.x * 8 + wid;
    const uint4* gm = (const uint4*)(g_gmin + (size_t)row * NGRP);
    uint4 va = gm[lane * 2], vb = gm[lane * 2 + 1];   // 16 halves = groups [lane*16, lane*16+16)
    float v[16];
    {
        uint32_t w[8] = {va.x, va.y, va.z, va.w, vb.x, vb.y, vb.z, vb.w};
#pragma unroll
        for (int i = 0; i < 8; i++) {
            float2 f = __half22float2(*(__half2*)&w[i]);
            v[i * 2] = f.x; v[i * 2 + 1] = f.y;
        }
    }
    float m = 3.4e38f;
#pragma unroll
    for (int i = 0; i < 16; i++) m = fminf(m, v[i]);
#pragma unroll
    for (int s = 16; s; s >>= 1) m = fminf(m, __shfl_xor_sync(0xffffffffu, m, s));
    float thr = m + MARGIN;
    if (lane == 0) g_best[row] = ~0ull;
#pragma unroll
    for (int i = 0; i < 16; i++) {
        if (v[i] <= thr) {
            int pos = atomicAdd(&g_count, 1);
            if (pos < PAIR_CAP) g_pairs[pos] = (unsigned)(row * NGRP + lane * 16 + i);
        }
    }
}

// ---------------- phase 2b: exact fp32 rescore of candidate groups ----------
__global__ void __launch_bounds__(256) k_rescore2(const float* __restrict__ emb) {
    __shared__ __align__(16) float zsh[8][256];
    int wid = threadIdx.x >> 5, lane = threadIdx.x & 31;
    int wi = blockIdx.x * 8 + wid;
    int stride = gridDim.x * 8;
    int cnt = g_count; if (cnt > PAIR_CAP) cnt = PAIR_CAP;

    for (int p = wi; p < cnt; p += stride) {
        unsigned e = g_pairs[p];
        int row = (int)(e >> 9), g = (int)(e & (NGRP - 1));
        float4* zs4 = (float4*)zsh[wid];
        const float4* zr4 = (const float4*)(g_zt + (size_t)row * DD);
        zs4[lane] = zr4[lane];
        zs4[lane + 32] = zr4[lane + 32];
        __syncwarp();
        float z2r = g_z2[row];
        int code = g * GSZ + (lane & 15);
        const float4* er = (const float4*)(emb + (size_t)code * DD);
        const float4* s4 = (const float4*)zsh[wid];
        float dot = 0.f;
#pragma unroll 16
        for (int d4 = 0; d4 < DD / 4; d4++) {
            float4 a = s4[d4], b2 = er[d4];
            dot = fmaf(a.x, b2.x, dot); dot = fmaf(a.y, b2.y, dot);
            dot = fmaf(a.z, b2.z, dot); dot = fmaf(a.w, b2.w, dot);
        }
        float dv = fmaf(-2.f, dot, z2r + g_e2[code]);
#pragma unroll
        for (int s = 16; s; s >>= 1) {
            float ov = __shfl_xor_sync(0xffffffffu, dv, s);
            int   oc = __shfl_xor_sync(0xffffffffu, code, s);
            if (ov < dv || (ov == dv && oc < code)) { dv = ov; code = oc; }
        }
        if (lane == 0) {
            unsigned long long key = ((unsigned long long)__float_as_uint(dv) << 13) | (unsigned)code;
            atomicMin(&g_best[row], key);
        }
        __syncwarp();
    }
}

// ---------------- epilogue: coalesced gather + loss -------------------------
__global__ void __launch_bounds__(256) k_quantize(
    const float* __restrict__ z, const float* __restrict__ emb, float* __restrict__ out) {
    __shared__ float esh[32][257];
    __shared__ int idxs[32];
    __shared__ float red[256];
    int t = threadIdx.x, lane = t & 31, w = t >> 5;
    int n0 = blockIdx.x * 32;
    if (t < 32) idxs[t] = (int)(g_best[n0 + t] & 0x1FFFull);
    __syncthreads();
#pragma unroll
    for (int q = 0; q < 4; q++) {
        int r = w * 4 + q;
        const float4* er = (const float4*)(emb + (size_t)idxs[r] * DD);
        float4 u = er[lane], v = er[lane + 32];
        int d0 = lane * 4;
        esh[r][d0 + 0] = u.x; esh[r][d0 + 1] = u.y; esh[r][d0 + 2] = u.z; esh[r][d0 + 3] = u.w;
        esh[r][128 + d0 + 0] = v.x; esh[r][128 + d0 + 1] = v.y;
        esh[r][128 + d0 + 2] = v.z; esh[r][128 + d0 + 3] = v.w;
    }
    __syncthreads();
    int b = n0 >> 10, s0 = n0 & 1023;
    const float* zp = z + (size_t)b * CHW + s0;
    float* op = out + (size_t)b * CHW + s0;
    float sq = 0.f;
    for (int d = w; d < DD; d += 8) {
        float e  = esh[lane][d];
        float zv = zp[(size_t)d * HW + lane];
        op[(size_t)d * HW + lane] = e;
        float diff = e - zv;
        sq = fmaf(diff, diff, sq);
    }
    red[t] = sq;
    __syncthreads();
#pragma unroll
    for (int st = 128; st; st >>= 1) {
        if (t < st) red[t] += red[t + st];
        __syncthreads();
    }
    if (t == 0) g_partial[blockIdx.x] = red[0];
}

__global__ void __launch_bounds__(256) k_finalize(float* __restrict__ out) {
    __shared__ float red[256];
    red[threadIdx.x] = g_partial[threadIdx.x] + g_partial[threadIdx.x + 256];
    __syncthreads();
#pragma unroll
    for (int st = 128; st; st >>= 1) {
        if (threadIdx.x < st) red[threadIdx.x] += red[threadIdx.x + st];
        __syncthreads();
    }
    if (threadIdx.x == 0) {
        float m = red[0] / 4194304.0f;
        out[(size_t)BB * CHW] = fmaf(0.25f, m, m);   // q_loss + 0.25*e_loss
    }
    for (int n = threadIdx.x; n < NN; n += 256)
        out[(size_t)BB * CHW + 1 + n] = (float)(int)(g_best[n] & 0x1FFFull);
}

// ---------------------------------------------------------------------------
extern "C" void kernel_launch(void* const* d_in, const int* in_sizes, int n_in,
                              void* d_out, int out_size) {
    const float* z   = (const float*)d_in[0];
    const float* emb = (const float*)d_in[1];
    float* out = (float*)d_out;

    cudaFuncSetAttribute(k_mma, cudaFuncAttributeMaxDynamicSharedMemorySize, SMEM_MMA);

    k_transpose<<<NN / 32, 256>>>(z);
    k_prep_e<<<KK / 8, 256>>>(emb);
    k_mma<<<dim3(NN / 128, 2), 256, SMEM_MMA>>>();
    k_gap<<<NN / 8, 256>>>();
    k_rescore2<<<NN / 8, 256>>>(emb);
    k_quantize<<<NN / 32, 256>>>(z, emb, out);
    k_finalize<<<1, 256>>>(out);
}

// round 11
// speedup vs baseline: 1.1486x; 1.1486x over previous
#include <cuda_runtime.h>
#include <cuda_bf16.h>
#include <cuda_fp16.h>
#include <stdint.h>

// Problem constants
#define BB  16
#define DD  256
#define HH  32
#define WW  32
#define NN  16384
#define KK  8192
#define CHW (DD*HH*WW)
#define HW  (HH*WW)

#define NCHUNK  128
#define GSZ     16
#define NGRP    (KK/GSZ)       // 512
#define MARGIN  2.5e-4f        // int8 approx error budget (~9 sigma)
#define PAIR_CAP (NN*64)
#define ZSCALE  16.0f          // z quant scale (|z|<7.94 fits s8)
#define ESCALE  1048576.0f     // e quant scale 2^20 (|e|<=1.22e-4 -> +-128, clamped)
#define DSCALE  (-1.1920928955078125e-7f)  // -2/(16*2^20) = -2^-23

#define SMEM_MMA 65536         // z tile 2x16KB + e double-buffer 2x16KB

// ---------------- device scratch (static globals; no allocation) -----------
__device__ __align__(16) float   g_zt[NN*DD];   // transposed z fp32 [n][d]
__device__ __align__(16) int8_t  g_z8[NN*DD];   // s8(z*16) [n][d]
__device__ __align__(16) int8_t  g_e8[KK*DD];   // s8(e*2^20) [k][d]
__device__ float          g_z2[NN];
__device__ float          g_e2[KK];
__device__ __align__(16) __half g_gmin[(size_t)NN*NGRP]; // [row][group] rd-fp16 min of (e2-2dot)
__device__ unsigned long long g_best[NN];
__device__ unsigned int   g_pairs[PAIR_CAP];
__device__ int            g_count;
__device__ float          g_partial[512];

// ---------------- helpers ---------------------------------------------------
__device__ __forceinline__ uint32_t smem_u32(const void* p) {
    uint32_t a;
    asm("{ .reg .u64 t; cvta.to.shared.u64 t, %1; cvt.u32.u64 %0, t; }" : "=r"(a) : "l"(p));
    return a;
}
__device__ __forceinline__ void ldsm4(uint32_t* r, uint32_t addr) {
    asm volatile("ldmatrix.sync.aligned.m8n8.x4.shared.b16 {%0,%1,%2,%3}, [%4];"
                 : "=r"(r[0]), "=r"(r[1]), "=r"(r[2]), "=r"(r[3]) : "r"(addr));
}
__device__ __forceinline__ void ldsm2(uint32_t* r, uint32_t addr) {
    asm volatile("ldmatrix.sync.aligned.m8n8.x2.shared.b16 {%0,%1}, [%2];"
                 : "=r"(r[0]), "=r"(r[1]) : "r"(addr));
}
__device__ __forceinline__ void mma_s8(int* c, const uint32_t* a, const uint32_t* b) {
    asm volatile("mma.sync.aligned.m16n8k32.row.col.s32.s8.s8.s32 "
                 "{%0,%1,%2,%3}, {%4,%5,%6,%7}, {%8,%9}, {%0,%1,%2,%3};"
                 : "+r"(c[0]), "+r"(c[1]), "+r"(c[2]), "+r"(c[3])
                 : "r"(a[0]), "r"(a[1]), "r"(a[2]), "r"(a[3]), "r"(b[0]), "r"(b[1]));
}
__device__ __forceinline__ void cp16(uint32_t dst, const void* src) {
    asm volatile("cp.async.cg.shared.global [%0], [%1], 16;" :: "r"(dst), "l"(src));
}
__device__ __forceinline__ int8_t f2s8(float x, float sc) {
    int v = __float2int_rn(x * sc);
    v = max(-127, min(127, v));
    return (int8_t)v;
}

// ---------------- prep: transpose z + s8 cast + z2 --------------------------
__global__ void __launch_bounds__(256) k_transpose(const float* __restrict__ z) {
    __shared__ float ts[256][33];
    int t = threadIdx.x, lane = t & 31, w = t >> 5;
    int n0 = blockIdx.x * 32;
    int b = n0 >> 10, s0 = n0 & 1023;
    const float* zp = z + (size_t)b * CHW + s0;
#pragma unroll 8
    for (int j = 0; j < 32; j++) {
        int d = j * 8 + w;
        ts[d][lane] = zp[(size_t)d * HW + lane];
    }
    __syncthreads();
#pragma unroll 8
    for (int j = 0; j < 32; j++) {
        float v = ts[t][j];
        size_t o = (size_t)(n0 + j) * DD + t;
        g_zt[o] = v;
        g_z8[o] = f2s8(v, ZSCALE);
    }
#pragma unroll
    for (int q = 0; q < 4; q++) {
        int nl = w * 4 + q;
        float s = 0.f;
#pragma unroll
        for (int jj = 0; jj < 8; jj++) { float v = ts[lane + 32 * jj][nl]; s = fmaf(v, v, s); }
#pragma unroll
        for (int m = 16; m; m >>= 1) s += __shfl_xor_sync(0xffffffffu, s, m);
        if (lane == 0) g_z2[n0 + nl] = s;
    }
}

// prep: s8 cast of scaled embeddings + e2 ; also zero pair counter
__global__ void __launch_bounds__(256) k_prep_e(const float* __restrict__ emb) {
    if (blockIdx.x == 0 && threadIdx.x == 0) g_count = 0;
    int k = blockIdx.x * 8 + (threadIdx.x >> 5);
    int lane = threadIdx.x & 31;
    const float* p = emb + (size_t)k * DD;
    float sum = 0.f;
#pragma unroll
    for (int j = 0; j < DD / 32; j++) {
        float v = p[lane + 32 * j];
        sum = fmaf(v, v, sum);
        g_e8[(size_t)k * DD + lane + 32 * j] = f2s8(v, ESCALE);
    }
#pragma unroll
    for (int m = 16; m; m >>= 1) sum += __shfl_xor_sync(0xffffffffu, sum, m);
    if (lane == 0) g_e2[k] = sum;
}

// ---------------- phase 1: s8 IMMA GEMM + per-group min ---------------------
// smem: [0,32KB) z tile (2 subtiles of 128x128B), [32KB,64KB) e double buffer.
__device__ __forceinline__ void stage_e(uint32_t sb, int s, int c0, int t) {
    int cc = s >> 1, dc = s & 1;
    const int8_t* esrc = g_e8 + (size_t)(c0 + cc) * NCHUNK * DD + dc * 128;
    uint32_t eb = sb + 32768u + (uint32_t)(s & 1) * 16384u;
#pragma unroll
    for (int j = 0; j < 4; j++) {
        int f = t + j * 256;               // 0..1023 16B chunks
        int r = f >> 3, ch = f & 7;
        cp16(eb + (uint32_t)(r * 128 + ((ch ^ (r & 7)) << 4)),
             esrc + (size_t)r * DD + ch * 16);
    }
    asm volatile("cp.async.commit_group;" ::: "memory");
}

__global__ void __launch_bounds__(256, 2) k_mma() {
    extern __shared__ __align__(1024) char smem[];
    uint32_t sb = smem_u32(smem);

    int t = threadIdx.x, lane = t & 31, wid = t >> 5;
    int wm = wid >> 2, wn = wid & 3;          // 2x4 warp grid, warp tile 64x32
    int n0 = blockIdx.x * 128;
    int c0 = blockIdx.y * 32;

    // z tile once: 128 rows x 256 s8 = 32KB, subtile per 128-dim half
    {
        const int8_t* zsrc = g_z8 + (size_t)n0 * DD;
#pragma unroll
        for (int j = 0; j < 8; j++) {
            int f = t + j * 256;              // 0..2047 16B chunks
            int r = f >> 4, c16 = f & 15;
            int dcs = c16 >> 3, ch = c16 & 7;
            cp16(sb + (uint32_t)(dcs * 16384 + r * 128 + ((ch ^ (r & 7)) << 4)),
                 zsrc + (size_t)r * DD + c16 * 16);
        }
    }
    stage_e(sb, 0, c0, t);                    // G0 = z + e-stage0

    int sub  = lane >> 3;
    int arow = wm * 64 + ((sub & 1) << 3) + (lane & 7);  // + mi*16
    int acoff = sub >> 1;
    int brow = wn * 32 + (lane & 7);                     // + ni*8
    int bsub = (lane >> 3) & 1;

    for (int cc = 0; cc < 32; cc++) {
        int c = c0 + cc;
        int acc[4][4][4];
#pragma unroll
        for (int mi = 0; mi < 4; mi++)
#pragma unroll
            for (int ni = 0; ni < 4; ni++)
#pragma unroll
                for (int q = 0; q < 4; q++) acc[mi][ni][q] = 0;

#pragma unroll
        for (int dc = 0; dc < 2; dc++) {
            int s = cc * 2 + dc;
            if (s + 1 < 64) {
                stage_e(sb, s + 1, c0, t);
                asm volatile("cp.async.wait_group 1;" ::: "memory");
            } else {
                asm volatile("cp.async.wait_group 0;" ::: "memory");
            }
            __syncthreads();
            uint32_t zb = sb + (uint32_t)dc * 16384u;              // z subtile = dc
            uint32_t eb = sb + 32768u + (uint32_t)(s & 1) * 16384u;
#pragma unroll
            for (int ks = 0; ks < 4; ks++) {
                uint32_t b[4][2];
#pragma unroll
                for (int ni = 0; ni < 4; ni++) {
                    int row = brow + ni * 8;
                    int ci  = ks * 2 + bsub;
                    ldsm2(b[ni], eb + (uint32_t)(row * 128 + ((ci ^ (row & 7)) << 4)));
                }
#pragma unroll
                for (int mi = 0; mi < 4; mi++) {
                    uint32_t a4[4];
                    int row = arow + mi * 16;
                    int ci  = ks * 2 + acoff;
                    ldsm4(a4, zb + (uint32_t)(row * 128 + ((ci ^ (row & 7)) << 4)));
#pragma unroll
                    for (int ni = 0; ni < 4; ni++)
                        mma_s8(acc[mi][ni], a4, b[ni]);
                }
            }
            __syncthreads();       // e buffer (s&1) reusable at s+2
        }
        // epilogue: per-row per-16-col-group min of (e2 - 2*dot), fp16 rd store
        float e2r[8];
#pragma unroll
        for (int ni = 0; ni < 4; ni++)
#pragma unroll
            for (int h = 0; h < 2; h++)
                e2r[ni * 2 + h] = __ldg(&g_e2[c * NCHUNK + wn * 32 + ni * 8 + (lane & 3) * 2 + h]);
#pragma unroll
        for (int mi = 0; mi < 4; mi++)
#pragma unroll
            for (int rh = 0; rh < 2; rh++) {
                float mp0 = 3.4e38f, mp1 = 3.4e38f;
#pragma unroll
                for (int ni = 0; ni < 4; ni++)
#pragma unroll
                    for (int h = 0; h < 2; h++) {
                        float dv = fmaf(DSCALE, __int2float_rn(acc[mi][ni][rh * 2 + h]),
                                        e2r[ni * 2 + h]);
                        if (ni < 2) { if (dv < mp0) mp0 = dv; }
                        else        { if (dv < mp1) mp1 = dv; }
                    }
                mp0 = fminf(mp0, __shfl_xor_sync(0xffffffffu, mp0, 1));
                mp0 = fminf(mp0, __shfl_xor_sync(0xffffffffu, mp0, 2));
                mp1 = fminf(mp1, __shfl_xor_sync(0xffffffffu, mp1, 1));
                mp1 = fminf(mp1, __shfl_xor_sync(0xffffffffu, mp1, 2));
                if ((lane & 3) == 0) {
                    int row = n0 + wm * 64 + mi * 16 + rh * 8 + (lane >> 2);
                    size_t base = (size_t)row * NGRP + c * 8 + wn * 2;
                    __half2 hv;
                    hv.x = __float2half_rd(mp0);
                    hv.y = __float2half_rd(mp1);
                    *(__half2*)(g_gmin + base) = hv;
                }
            }
    }
}

// ---------------- phase 2a: scan gmin (fp16), emit candidate pairs ----------
__global__ void __launch_bounds__(256) k_gap() {
    int wid = threadIdx.x >> 5, lane = threadIdx.x & 31;
    int row = blockIdx.x * 8 + wid;
    const uint4* gm = (const uint4*)(g_gmin + (size_t)row * NGRP);
    uint4 va = gm[lane * 2], vb = gm[lane * 2 + 1];   // 16 halves = groups [lane*16, lane*16+16)
    float v[16];
    {
        uint32_t w[8] = {va.x, va.y, va.z, va.w, vb.x, vb.y, vb.z, vb.w};
#pragma unroll
        for (int i = 0; i < 8; i++) {
            float2 f = __half22float2(*(__half2*)&w[i]);
            v[i * 2] = f.x; v[i * 2 + 1] = f.y;
        }
    }
    float m = 3.4e38f;
#pragma unroll
    for (int i = 0; i < 16; i++) m = fminf(m, v[i]);
#pragma unroll
    for (int s = 16; s; s >>= 1) m = fminf(m, __shfl_xor_sync(0xffffffffu, m, s));
    float thr = m + MARGIN;
    if (lane == 0) g_best[row] = ~0ull;
#pragma unroll
    for (int i = 0; i < 16; i++) {
        if (v[i] <= thr) {
            int pos = atomicAdd(&g_count, 1);
            if (pos < PAIR_CAP) g_pairs[pos] = (unsigned)(row * NGRP + lane * 16 + i);
        }
    }
}

// ---------------- phase 2b: exact fp32 rescore of candidate groups ----------
__global__ void __launch_bounds__(256) k_rescore2(const float* __restrict__ emb) {
    __shared__ __align__(16) float zsh[8][256];
    int wid = threadIdx.x >> 5, lane = threadIdx.x & 31;
    int wi = blockIdx.x * 8 + wid;
    int stride = gridDim.x * 8;
    int cnt = g_count; if (cnt > PAIR_CAP) cnt = PAIR_CAP;

    for (int p = wi; p < cnt; p += stride) {
        unsigned e = g_pairs[p];
        int row = (int)(e >> 9), g = (int)(e & (NGRP - 1));
        float4* zs4 = (float4*)zsh[wid];
        const float4* zr4 = (const float4*)(g_zt + (size_t)row * DD);
        zs4[lane] = zr4[lane];
        zs4[lane + 32] = zr4[lane + 32];
        __syncwarp();
        float z2r = g_z2[row];
        int code = g * GSZ + (lane & 15);
        const float4* er = (const float4*)(emb + (size_t)code * DD);
        const float4* s4 = (const float4*)zsh[wid];
        float dot = 0.f;
#pragma unroll 16
        for (int d4 = 0; d4 < DD / 4; d4++) {
            float4 a = s4[d4], b2 = er[d4];
            dot = fmaf(a.x, b2.x, dot); dot = fmaf(a.y, b2.y, dot);
            dot = fmaf(a.z, b2.z, dot); dot = fmaf(a.w, b2.w, dot);
        }
        float dv = fmaf(-2.f, dot, z2r + g_e2[code]);
#pragma unroll
        for (int s = 16; s; s >>= 1) {
            float ov = __shfl_xor_sync(0xffffffffu, dv, s);
            int   oc = __shfl_xor_sync(0xffffffffu, code, s);
            if (ov < dv || (ov == dv && oc < code)) { dv = ov; code = oc; }
        }
        if (lane == 0) {
            unsigned long long key = ((unsigned long long)__float_as_uint(dv) << 13) | (unsigned)code;
            atomicMin(&g_best[row], key);
        }
        __syncwarp();
    }
}

// ---------------- epilogue: coalesced gather + loss -------------------------
__global__ void __launch_bounds__(256) k_quantize(
    const float* __restrict__ z, const float* __restrict__ emb, float* __restrict__ out) {
    __shared__ float esh[32][257];
    __shared__ int idxs[32];
    __shared__ float red[256];
    int t = threadIdx.x, lane = t & 31, w = t >> 5;
    int n0 = blockIdx.x * 32;
    if (t < 32) idxs[t] = (int)(g_best[n0 + t] & 0x1FFFull);
    __syncthreads();
#pragma unroll
    for (int q = 0; q < 4; q++) {
        int r = w * 4 + q;
        const float4* er = (const float4*)(emb + (size_t)idxs[r] * DD);
        float4 u = er[lane], v = er[lane + 32];
        int d0 = lane * 4;
        esh[r][d0 + 0] = u.x; esh[r][d0 + 1] = u.y; esh[r][d0 + 2] = u.z; esh[r][d0 + 3] = u.w;
        esh[r][128 + d0 + 0] = v.x; esh[r][128 + d0 + 1] = v.y;
        esh[r][128 + d0 + 2] = v.z; esh[r][128 + d0 + 3] = v.w;
    }
    __syncthreads();
    int b = n0 >> 10, s0 = n0 & 1023;
    const float* zp = z + (size_t)b * CHW + s0;
    float* op = out + (size_t)b * CHW + s0;
    float sq = 0.f;
    for (int d = w; d < DD; d += 8) {
        float e  = esh[lane][d];
        float zv = zp[(size_t)d * HW + lane];
        op[(size_t)d * HW + lane] = e;
        float diff = e - zv;
        sq = fmaf(diff, diff, sq);
    }
    red[t] = sq;
    __syncthreads();
#pragma unroll
    for (int st = 128; st; st >>= 1) {
        if (t < st) red[t] += red[t + st];
        __syncthreads();
    }
    if (t == 0) g_partial[blockIdx.x] = red[0];
}

__global__ void __launch_bounds__(256) k_finalize(float* __restrict__ out) {
    __shared__ float red[256];
    red[threadIdx.x] = g_partial[threadIdx.x] + g_partial[threadIdx.x + 256];
    __syncthreads();
#pragma unroll
    for (int st = 128; st; st >>= 1) {
        if (threadIdx.x < st) red[threadIdx.x] += red[threadIdx.x + st];
        __syncthreads();
    }
    if (threadIdx.x == 0) {
        float m = red[0] / 4194304.0f;
        out[(size_t)BB * CHW] = fmaf(0.25f, m, m);   // q_loss + 0.25*e_loss
    }
    for (int n = threadIdx.x; n < NN; n += 256)
        out[(size_t)BB * CHW + 1 + n] = (float)(int)(g_best[n] & 0x1FFFull);
}

// ---------------------------------------------------------------------------
extern "C" void kernel_launch(void* const* d_in, const int* in_sizes, int n_in,
                              void* d_out, int out_size) {
    const float* z   = (const float*)d_in[0];
    const float* emb = (const float*)d_in[1];
    float* out = (float*)d_out;

    cudaFuncSetAttribute(k_mma, cudaFuncAttributeMaxDynamicSharedMemorySize, SMEM_MMA);

    k_transpose<<<NN / 32, 256>>>(z);
    k_prep_e<<<KK / 8, 256>>>(emb);
    k_mma<<<dim3(NN / 128, 2), 256, SMEM_MMA>>>();
    k_gap<<<NN / 8, 256>>>();
    k_rescore2<<<NN / 8, 256>>>(emb);
    k_quantize<<<NN / 32, 256>>>(z, emb, out);
    k_finalize<<<1, 256>>>(out);
}

// round 12
// speedup vs baseline: 2.1512x; 1.8728x over previous
#include <cuda_runtime.h>
#include <cuda_bf16.h>
#include <cuda_fp16.h>
#include <stdint.h>

// Problem constants
#define BB  16
#define DD  256
#define HH  32
#define WW  32
#define NN  16384
#define KK  8192
#define CHW (DD*HH*WW)
#define HW  (HH*WW)

#define NCHUNK  128
#define GSZ     16
#define NGRP    (KK/GSZ)       // 512
#define MARGIN  2.5e-4f        // bf16 approx error budget
#define PAIR_CAP (NN*64)

#define SMEM_MMA (65536 + 32768)   // z tile 64KB (4x16KB) + e double-buffer 2x16KB

// ---------------- device scratch (static globals; no allocation) -----------
__device__ __align__(16) float          g_zt[NN*DD];   // transposed z fp32 [n][d]
__device__ __align__(16) __nv_bfloat16  g_zbf[NN*DD];  // bf16 [n][d]
__device__ __align__(16) __nv_bfloat16  g_ebf[KK*DD];  // bf16 [k][d]
__device__ float          g_z2[NN];
__device__ float          g_e2[KK];
__device__ __align__(16) __half g_gmin[(size_t)NN*NGRP]; // [row][group] rd-fp16 min of (e2-2dot)
__device__ unsigned long long g_best[NN];
__device__ unsigned int   g_pairs[PAIR_CAP];
__device__ int            g_count;
__device__ float          g_partial[512];

// ---------------- helpers ---------------------------------------------------
__device__ __forceinline__ uint32_t smem_u32(const void* p) {
    uint32_t a;
    asm("{ .reg .u64 t; cvta.to.shared.u64 t, %1; cvt.u32.u64 %0, t; }" : "=r"(a) : "l"(p));
    return a;
}
__device__ __forceinline__ void ldsm4(uint32_t* r, uint32_t addr) {
    asm volatile("ldmatrix.sync.aligned.m8n8.x4.shared.b16 {%0,%1,%2,%3}, [%4];"
                 : "=r"(r[0]), "=r"(r[1]), "=r"(r[2]), "=r"(r[3]) : "r"(addr));
}
__device__ __forceinline__ void ldsm2(uint32_t* r, uint32_t addr) {
    asm volatile("ldmatrix.sync.aligned.m8n8.x2.shared.b16 {%0,%1}, [%2];"
                 : "=r"(r[0]), "=r"(r[1]) : "r"(addr));
}
__device__ __forceinline__ void mma_bf16(float* c, const uint32_t* a, const uint32_t* b) {
    asm volatile("mma.sync.aligned.m16n8k16.row.col.f32.bf16.bf16.f32 "
                 "{%0,%1,%2,%3}, {%4,%5,%6,%7}, {%8,%9}, {%0,%1,%2,%3};"
                 : "+f"(c[0]), "+f"(c[1]), "+f"(c[2]), "+f"(c[3])
                 : "r"(a[0]), "r"(a[1]), "r"(a[2]), "r"(a[3]), "r"(b[0]), "r"(b[1]));
}
__device__ __forceinline__ void cp16(uint32_t dst, const void* src) {
    asm volatile("cp.async.cg.shared.global [%0], [%1], 16;" :: "r"(dst), "l"(src));
}

// ---------------- prep: transpose z + bf16 cast + z2 ------------------------
__global__ void __launch_bounds__(256) k_transpose(const float* __restrict__ z) {
    __shared__ float ts[256][33];
    int t = threadIdx.x, lane = t & 31, w = t >> 5;
    int n0 = blockIdx.x * 32;
    int b = n0 >> 10, s0 = n0 & 1023;
    const float* zp = z + (size_t)b * CHW + s0;
#pragma unroll 8
    for (int j = 0; j < 32; j++) {
        int d = j * 8 + w;
        ts[d][lane] = zp[(size_t)d * HW + lane];
    }
    __syncthreads();
#pragma unroll 8
    for (int j = 0; j < 32; j++) {
        float v = ts[t][j];
        size_t o = (size_t)(n0 + j) * DD + t;
        g_zt[o]  = v;
        g_zbf[o] = __float2bfloat16_rn(v);
    }
#pragma unroll
    for (int q = 0; q < 4; q++) {
        int nl = w * 4 + q;
        float s = 0.f;
#pragma unroll
        for (int jj = 0; jj < 8; jj++) { float v = ts[lane + 32 * jj][nl]; s = fmaf(v, v, s); }
#pragma unroll
        for (int m = 16; m; m >>= 1) s += __shfl_xor_sync(0xffffffffu, s, m);
        if (lane == 0) g_z2[n0 + nl] = s;
    }
}

// prep: bf16 cast of embeddings + e2 ; also zero pair counter
__global__ void __launch_bounds__(256) k_prep_e(const float* __restrict__ emb) {
    if (blockIdx.x == 0 && threadIdx.x == 0) g_count = 0;
    int k = blockIdx.x * 8 + (threadIdx.x >> 5);
    int lane = threadIdx.x & 31;
    const float* p = emb + (size_t)k * DD;
    float sum = 0.f;
#pragma unroll
    for (int j = 0; j < DD / 32; j++) {
        float v = p[lane + 32 * j];
        sum = fmaf(v, v, sum);
        g_ebf[(size_t)k * DD + lane + 32 * j] = __float2bfloat16_rn(v);
    }
#pragma unroll
    for (int m = 16; m; m >>= 1) sum += __shfl_xor_sync(0xffffffffu, sum, m);
    if (lane == 0) g_e2[k] = sum;
}

// ---------------- phase 1: bf16 HMMA GEMM + per-group min -------------------
// smem: [0,64KB) z tile (4 subtiles of 128x64 bf16), [64KB,96KB) e dbl buffer.
// stage s = cc*4+dc : e chunk cc, 64-d slice dc (16KB).
__device__ __forceinline__ void stage_e(uint32_t sb, int s, int c0, int t) {
    int cc = s >> 2, dc = s & 3;
    const __nv_bfloat16* esrc = g_ebf + (size_t)(c0 + cc) * NCHUNK * DD + dc * 64;
    uint32_t eb = sb + 65536u + (uint32_t)(s & 1) * 16384u;
#pragma unroll
    for (int j = 0; j < 4; j++) {
        int f = t + j * 256;               // 0..1023 16B chunks
        int r = f >> 3, ch = f & 7;
        cp16(eb + (uint32_t)(r * 128 + ((ch ^ (r & 7)) << 4)),
             esrc + (size_t)r * DD + ch * 8);
    }
    asm volatile("cp.async.commit_group;" ::: "memory");
}

__global__ void __launch_bounds__(256, 2) k_mma() {
    extern __shared__ __align__(1024) char smem[];
    uint32_t sb = smem_u32(smem);

    int t = threadIdx.x, lane = t & 31, wid = t >> 5;
    int wm = wid >> 2, wn = wid & 3;          // 2x4 warp grid, warp tile 64x32
    int n0 = blockIdx.x * 128;
    int c0 = blockIdx.y * 32;

    // z tile once: 128 rows x 256 bf16 = 64KB, subtile dcs per 64-d slice
    {
        const __nv_bfloat16* zsrc = g_zbf + (size_t)n0 * DD;
#pragma unroll
        for (int j = 0; j < 16; j++) {
            int f = t + j * 256;              // 0..4095 16B chunks
            int r = f >> 5, c32 = f & 31;     // row, 16B-chunk within 512B row
            int dcs = c32 >> 3, ch = c32 & 7;
            cp16(sb + (uint32_t)(dcs * 16384 + r * 128 + ((ch ^ (r & 7)) << 4)),
                 zsrc + (size_t)r * DD + c32 * 8);
        }
    }
    stage_e(sb, 0, c0, t);                    // G0 = z + e-stage0

    int sub  = lane >> 3;
    int arow = wm * 64 + ((sub & 1) << 3) + (lane & 7);  // + mi*16
    int acoff = sub >> 1;
    int brow = wn * 32 + (lane & 7);                     // + ni*8
    int bsub = (lane >> 3) & 1;

    for (int cc = 0; cc < 32; cc++) {
        int c = c0 + cc;
        float acc[4][4][4];
#pragma unroll
        for (int mi = 0; mi < 4; mi++)
#pragma unroll
            for (int ni = 0; ni < 4; ni++)
#pragma unroll
                for (int q = 0; q < 4; q++) acc[mi][ni][q] = 0.f;

#pragma unroll
        for (int dc = 0; dc < 4; dc++) {
            int s = cc * 4 + dc;
            if (s + 1 < 128) {
                stage_e(sb, s + 1, c0, t);
                asm volatile("cp.async.wait_group 1;" ::: "memory");
            } else {
                asm volatile("cp.async.wait_group 0;" ::: "memory");
            }
            __syncthreads();
            uint32_t zb = sb + (uint32_t)dc * 16384u;              // z subtile = dc
            uint32_t eb = sb + 65536u + (uint32_t)(s & 1) * 16384u;
#pragma unroll
            for (int ks = 0; ks < 4; ks++) {
                uint32_t b[4][2];
#pragma unroll
                for (int ni = 0; ni < 4; ni++) {
                    int row = brow + ni * 8;
                    int ci  = ks * 2 + bsub;
                    ldsm2(b[ni], eb + (uint32_t)(row * 128 + ((ci ^ (row & 7)) << 4)));
                }
#pragma unroll
                for (int mi = 0; mi < 4; mi++) {
                    uint32_t a4[4];
                    int row = arow + mi * 16;
                    int ci  = ks * 2 + acoff;
                    ldsm4(a4, zb + (uint32_t)(row * 128 + ((ci ^ (row & 7)) << 4)));
#pragma unroll
                    for (int ni = 0; ni < 4; ni++)
                        mma_bf16(acc[mi][ni], a4, b[ni]);
                }
            }
            __syncthreads();       // e buffer (s&1) reusable at s+2
        }
        // epilogue: per-row per-16-col-group min of (e2 - 2*dot), fp16 rd store
        float e2r[8];
#pragma unroll
        for (int ni = 0; ni < 4; ni++)
#pragma unroll
            for (int h = 0; h < 2; h++)
                e2r[ni * 2 + h] = __ldg(&g_e2[c * NCHUNK + wn * 32 + ni * 8 + (lane & 3) * 2 + h]);
#pragma unroll
        for (int mi = 0; mi < 4; mi++)
#pragma unroll
            for (int rh = 0; rh < 2; rh++) {
                float mp0 = 3.4e38f, mp1 = 3.4e38f;
#pragma unroll
                for (int ni = 0; ni < 4; ni++)
#pragma unroll
                    for (int h = 0; h < 2; h++) {
                        float dv = fmaf(-2.f, acc[mi][ni][rh * 2 + h], e2r[ni * 2 + h]);
                        if (ni < 2) { if (dv < mp0) mp0 = dv; }
                        else        { if (dv < mp1) mp1 = dv; }
                    }
                mp0 = fminf(mp0, __shfl_xor_sync(0xffffffffu, mp0, 1));
                mp0 = fminf(mp0, __shfl_xor_sync(0xffffffffu, mp0, 2));
                mp1 = fminf(mp1, __shfl_xor_sync(0xffffffffu, mp1, 1));
                mp1 = fminf(mp1, __shfl_xor_sync(0xffffffffu, mp1, 2));
                if ((lane & 3) == 0) {
                    int row = n0 + wm * 64 + mi * 16 + rh * 8 + (lane >> 2);
                    size_t base = (size_t)row * NGRP + c * 8 + wn * 2;
                    __half2 hv;
                    hv.x = __float2half_rd(mp0);
                    hv.y = __float2half_rd(mp1);
                    *(__half2*)(g_gmin + base) = hv;
                }
            }
    }
}

// ---------------- phase 2a: scan gmin (fp16), emit candidate pairs ----------
__global__ void __launch_bounds__(256) k_gap() {
    int wid = threadIdx.x >> 5, lane = threadIdx.x & 31;
    int row = blockIdx.x * 8 + wid;
    const uint4* gm = (const uint4*)(g_gmin + (size_t)row * NGRP);
    uint4 va = gm[lane * 2], vb = gm[lane * 2 + 1];   // 16 halves = groups [lane*16, lane*16+16)
    float v[16];
    {
        uint32_t w[8] = {va.x, va.y, va.z, va.w, vb.x, vb.y, vb.z, vb.w};
#pragma unroll
        for (int i = 0; i < 8; i++) {
            float2 f = __half22float2(*(__half2*)&w[i]);
            v[i * 2] = f.x; v[i * 2 + 1] = f.y;
        }
    }
    float m = 3.4e38f;
#pragma unroll
    for (int i = 0; i < 16; i++) m = fminf(m, v[i]);
#pragma unroll
    for (int s = 16; s; s >>= 1) m = fminf(m, __shfl_xor_sync(0xffffffffu, m, s));
    float thr = m + MARGIN;
    if (lane == 0) g_best[row] = ~0ull;
#pragma unroll
    for (int i = 0; i < 16; i++) {
        if (v[i] <= thr) {
            int pos = atomicAdd(&g_count, 1);
            if (pos < PAIR_CAP) g_pairs[pos] = (unsigned)(row * NGRP + lane * 16 + i);
        }
    }
}

// ---------------- phase 2b: exact fp32 rescore of candidate groups ----------
__global__ void __launch_bounds__(256) k_rescore2(const float* __restrict__ emb) {
    __shared__ __align__(16) float zsh[8][256];
    int wid = threadIdx.x >> 5, lane = threadIdx.x & 31;
    int wi = blockIdx.x * 8 + wid;
    int stride = gridDim.x * 8;
    int cnt = g_count; if (cnt > PAIR_CAP) cnt = PAIR_CAP;

    for (int p = wi; p < cnt; p += stride) {
        unsigned e = g_pairs[p];
        int row = (int)(e >> 9), g = (int)(e & (NGRP - 1));
        float4* zs4 = (float4*)zsh[wid];
        const float4* zr4 = (const float4*)(g_zt + (size_t)row * DD);
        zs4[lane] = zr4[lane];
        zs4[lane + 32] = zr4[lane + 32];
        __syncwarp();
        float z2r = g_z2[row];
        int code = g * GSZ + (lane & 15);
        const float4* er = (const float4*)(emb + (size_t)code * DD);
        const float4* s4 = (const float4*)zsh[wid];
        float dot = 0.f;
#pragma unroll 16
        for (int d4 = 0; d4 < DD / 4; d4++) {
            float4 a = s4[d4], b2 = er[d4];
            dot = fmaf(a.x, b2.x, dot); dot = fmaf(a.y, b2.y, dot);
            dot = fmaf(a.z, b2.z, dot); dot = fmaf(a.w, b2.w, dot);
        }
        float dv = fmaf(-2.f, dot, z2r + g_e2[code]);
#pragma unroll
        for (int s = 16; s; s >>= 1) {
            float ov = __shfl_xor_sync(0xffffffffu, dv, s);
            int   oc = __shfl_xor_sync(0xffffffffu, code, s);
            if (ov < dv || (ov == dv && oc < code)) { dv = ov; code = oc; }
        }
        if (lane == 0) {
            unsigned long long key = ((unsigned long long)__float_as_uint(dv) << 13) | (unsigned)code;
            atomicMin(&g_best[row], key);
        }
        __syncwarp();
    }
}

// ---------------- epilogue: coalesced gather + loss -------------------------
__global__ void __launch_bounds__(256) k_quantize(
    const float* __restrict__ z, const float* __restrict__ emb, float* __restrict__ out) {
    __shared__ float esh[32][257];
    __shared__ int idxs[32];
    __shared__ float red[256];
    int t = threadIdx.x, lane = t & 31, w = t >> 5;
    int n0 = blockIdx.x * 32;
    if (t < 32) idxs[t] = (int)(g_best[n0 + t] & 0x1FFFull);
    __syncthreads();
#pragma unroll
    for (int q = 0; q < 4; q++) {
        int r = w * 4 + q;
        const float4* er = (const float4*)(emb + (size_t)idxs[r] * DD);
        float4 u = er[lane], v = er[lane + 32];
        int d0 = lane * 4;
        esh[r][d0 + 0] = u.x; esh[r][d0 + 1] = u.y; esh[r][d0 + 2] = u.z; esh[r][d0 + 3] = u.w;
        esh[r][128 + d0 + 0] = v.x; esh[r][128 + d0 + 1] = v.y;
        esh[r][128 + d0 + 2] = v.z; esh[r][128 + d0 + 3] = v.w;
    }
    __syncthreads();
    int b = n0 >> 10, s0 = n0 & 1023;
    const float* zp = z + (size_t)b * CHW + s0;
    float* op = out + (size_t)b * CHW + s0;
    float sq = 0.f;
    for (int d = w; d < DD; d += 8) {
        float e  = esh[lane][d];
        float zv = zp[(size_t)d * HW + lane];
        op[(size_t)d * HW + lane] = e;
        float diff = e - zv;
        sq = fmaf(diff, diff, sq);
    }
    red[t] = sq;
    __syncthreads();
#pragma unroll
    for (int st = 128; st; st >>= 1) {
        if (t < st) red[t] += red[t + st];
        __syncthreads();
    }
    if (t == 0) g_partial[blockIdx.x] = red[0];
}

__global__ void __launch_bounds__(256) k_finalize(float* __restrict__ out) {
    __shared__ float red[256];
    red[threadIdx.x] = g_partial[threadIdx.x] + g_partial[threadIdx.x + 256];
    __syncthreads();
#pragma unroll
    for (int st = 128; st; st >>= 1) {
        if (threadIdx.x < st) red[threadIdx.x] += red[threadIdx.x + st];
        __syncthreads();
    }
    if (threadIdx.x == 0) {
        float m = red[0] / 4194304.0f;
        out[(size_t)BB * CHW] = fmaf(0.25f, m, m);   // q_loss + 0.25*e_loss
    }
    for (int n = threadIdx.x; n < NN; n += 256)
        out[(size_t)BB * CHW + 1 + n] = (float)(int)(g_best[n] & 0x1FFFull);
}

// ---------------------------------------------------------------------------
extern "C" void kernel_launch(void* const* d_in, const int* in_sizes, int n_in,
                              void* d_out, int out_size) {
    const float* z   = (const float*)d_in[0];
    const float* emb = (const float*)d_in[1];
    float* out = (float*)d_out;

    cudaFuncSetAttribute(k_mma, cudaFuncAttributeMaxDynamicSharedMemorySize, SMEM_MMA);

    k_transpose<<<NN / 32, 256>>>(z);
    k_prep_e<<<KK / 8, 256>>>(emb);
    k_mma<<<dim3(NN / 128, 2), 256, SMEM_MMA>>>();
    k_gap<<<NN / 8, 256>>>();
    k_rescore2<<<NN / 8, 256>>>(emb);
    k_quantize<<<NN / 32, 256>>>(z, emb, out);
    k_finalize<<<1, 256>>>(out);
}